// round 1
// baseline (speedup 1.0000x reference)
#include <cuda_runtime.h>
#include <cuda_bf16.h>
#include <math.h>

// Problem constants
#define NPIL  60000
#define PPTS  32
#define COUT  64
#define NTOT  ((double)NPIL * (double)PPTS)

// Static device scratch (allocation-free rule): per-pillar per-channel max/min of raw linear output
__device__ float g_pmax[NPIL * COUT];
__device__ float g_pmin[NPIL * COUT];
// Global BN accumulators
__device__ double g_sum[COUT];
__device__ double g_sumsq[COUT];

// ---------------------------------------------------------------------------
// Kernel 0: zero the accumulators (graph replays must be deterministic)
// ---------------------------------------------------------------------------
__global__ void k_zero() {
    int t = threadIdx.x;
    if (t < COUT) { g_sum[t] = 0.0; g_sumsq[t] = 0.0; }
}

// ---------------------------------------------------------------------------
// Kernel 1: per-pillar linear (collapsed to 4 effective channels) + running
// channel sums / sums-of-squares + per-pillar max/min over points.
//
// Block = 256 threads = 4 pillars x 64 channel-threads.
// Stage phase: warps 0..3 each own one pillar; lane p loads point p (float4,
// fully coalesced 512B per pillar), warp-reduces the xyz sum over ALL 32
// points (reference divides the unmasked sum by num_voxels).
// Compute phase: thread t handles pillar (t>>6), channel (t&63); loops over
// the nv valid points from shared memory (same-address broadcast LDS.128).
// ---------------------------------------------------------------------------
__global__ __launch_bounds__(256, 8)
void k_stats(const float4* __restrict__ feats,
             const int*    __restrict__ nvox,
             const int*    __restrict__ coords,
             const float*  __restrict__ W)
{
    __shared__ float4 sh_pts[4][PPTS];
    __shared__ float  sh_hdr[4][8];   // Sx,Sy,Sz,rcp_nv,cx,cy,cz,nv_f
    __shared__ float  sred[256];
    __shared__ float  ssred[256];

    const int t    = threadIdx.x;
    const int o    = t & 63;          // channel
    const int g    = t >> 6;          // pillar slot within block
    const int warp = t >> 5;
    const int lane = t & 31;

    // Per-thread channel weights (fixed channel across all pillars)
    const float* Wr = W + o * 10;
    const float w4 = Wr[4], w5 = Wr[5], w6 = Wr[6];
    const float w7 = Wr[7], w8 = Wr[8], w9 = Wr[9];
    const float e0 = Wr[0] + w4 + w7;   // effective xyz weights
    const float e1 = Wr[1] + w5 + w8;
    const float e2 = Wr[2] + w6 + w9;
    const float e3 = Wr[3];             // intensity weight

    float s_acc  = 0.0f;
    float ss_acc = 0.0f;

    for (int base = blockIdx.x * 4; base < NPIL; base += gridDim.x * 4) {
        // ---- stage: warps 0..3 load points for pillars base..base+3 ----
        if (warp < 4) {
            const int pil = base + warp;
            float4 pt = feats[pil * PPTS + lane];
            sh_pts[warp][lane] = pt;
            // xyz sum over ALL 32 points (reference sums unmasked)
            float sx = pt.x, sy = pt.y, sz = pt.z;
            #pragma unroll
            for (int d = 16; d; d >>= 1) {
                sx += __shfl_xor_sync(0xFFFFFFFFu, sx, d);
                sy += __shfl_xor_sync(0xFFFFFFFFu, sy, d);
                sz += __shfl_xor_sync(0xFFFFFFFFu, sz, d);
            }
            if (lane == 0) {
                int nv = nvox[pil];
                sh_hdr[warp][0] = sx;
                sh_hdr[warp][1] = sy;
                sh_hdr[warp][2] = sz;
                sh_hdr[warp][3] = 1.0f / (float)nv;
                sh_hdr[warp][7] = (float)nv;
            }
            if (lane < 3) {
                // coords row = (batch, z_idx, y_idx, x_idx)
                int c = coords[pil * 4 + (lane + 1)];
                float ctr;
                int slot;
                if (lane == 0)      { ctr = (float)c * 4.0f - 1.0f;  slot = 6; } // cz
                else if (lane == 1) { ctr = (float)c * 0.2f - 39.9f; slot = 5; } // cy
                else                { ctr = (float)c * 0.2f + 0.1f;  slot = 4; } // cx
                sh_hdr[warp][slot] = ctr;
            }
        }
        __syncthreads();

        // ---- compute: 64 channel-threads per pillar ----
        {
            const float Sx  = sh_hdr[g][0];
            const float Sy  = sh_hdr[g][1];
            const float Sz  = sh_hdr[g][2];
            const float rnv = sh_hdr[g][3];
            const float cx  = sh_hdr[g][4];
            const float cy  = sh_hdr[g][5];
            const float cz  = sh_hdr[g][6];
            const int   nv  = (int)sh_hdr[g][7];

            // const_n[o] = -mean . W[:,4:7] - center . W[:,7:10]
            const float cst = -(Sx * w4 + Sy * w5 + Sz * w6) * rnv
                              -(cx * w7 + cy * w8 + cz * w9);

            float mx = -3.402823466e38f;
            float mn =  3.402823466e38f;
            #pragma unroll 4
            for (int p = 0; p < nv; p++) {
                float4 pt = sh_pts[g][p];
                float v = fmaf(e0, pt.x,
                          fmaf(e1, pt.y,
                          fmaf(e2, pt.z,
                          fmaf(e3, pt.w, cst))));
                mx = fmaxf(mx, v);
                mn = fminf(mn, v);
                s_acc  += v;
                ss_acc  = fmaf(v, v, ss_acc);
            }
            if (nv < PPTS) {          // masked points contribute exact zeros
                mx = fmaxf(mx, 0.0f);
                mn = fminf(mn, 0.0f);
            }
            const int pil = base + g;
            g_pmax[pil * COUT + o] = mx;
            g_pmin[pil * COUT + o] = mn;
        }
        __syncthreads();
    }

    // ---- block reduction of channel sums, one atomic pair per channel ----
    sred[t]  = s_acc;
    ssred[t] = ss_acc;
    __syncthreads();
    if (t < 128) { sred[t] += sred[t + 128]; ssred[t] += ssred[t + 128]; }
    __syncthreads();
    if (t < 64) {
        double s  = (double)sred[t]  + (double)sred[t + 64];
        double ss = (double)ssred[t] + (double)ssred[t + 64];
        atomicAdd(&g_sum[t],   s);
        atomicAdd(&g_sumsq[t], ss);
    }
}

// ---------------------------------------------------------------------------
// Kernel 2: finalize BN per block (cheap, redundant) then stream
// scratch max/min -> affine -> relu -> output.
// ---------------------------------------------------------------------------
__global__ __launch_bounds__(256)
void k_out(const float* __restrict__ gamma,
           const float* __restrict__ beta,
           float* __restrict__ out)
{
    __shared__ float sc[COUT];
    __shared__ float sb[COUT];
    if (threadIdx.x < COUT) {
        const int o = threadIdx.x;
        double m   = g_sum[o]   / NTOT;
        double var = g_sumsq[o] / NTOT - m * m;
        float  s   = gamma[o] / (float)sqrt(var + 1e-3);
        sc[o] = s;
        sb[o] = beta[o] - (float)m * s;
    }
    __syncthreads();

    const int total  = NPIL * COUT;
    const int stride = gridDim.x * blockDim.x;
    for (int idx = blockIdx.x * blockDim.x + threadIdx.x; idx < total; idx += stride) {
        const int o = idx & 63;
        const float s = sc[o];
        const float b = sb[o];
        float e;
        if (s >= 0.0f) e = __ldg(&g_pmax[idx]);   // gamma>0 path: min array never touched
        else           e = __ldg(&g_pmin[idx]);
        out[idx] = fmaxf(0.0f, fmaf(s, e, b));
    }
}

// ---------------------------------------------------------------------------
extern "C" void kernel_launch(void* const* d_in, const int* in_sizes, int n_in,
                              void* d_out, int out_size)
{
    const float4* feats  = (const float4*)d_in[0];
    const int*    nvox   = (const int*)   d_in[1];
    const int*    coords = (const int*)   d_in[2];
    const float*  W      = (const float*) d_in[3];
    const float*  gamma  = (const float*) d_in[4];
    const float*  beta   = (const float*) d_in[5];
    float*        out    = (float*)       d_out;

    k_zero<<<1, 64>>>();
    k_stats<<<592, 256>>>(feats, nvox, coords, W);
    k_out<<<1184, 256>>>(gamma, beta, out);
}

// round 2
// speedup vs baseline: 1.5882x; 1.5882x over previous
#include <cuda_runtime.h>
#include <cuda_bf16.h>
#include <math.h>
#include <float.h>

// Problem constants
#define NPIL  60000
#define PPTS  32
#define COUT  64
#define NTOT  ((double)NPIL * (double)PPTS)

#define STATS_BLOCKS 592     // 4 blocks/SM x 148 SMs
#define OUT_BLOCKS   1184

// Static device scratch (allocation-free rule)
__device__ float  g_pmax[NPIL * COUT];
__device__ float  g_pmin[NPIL * COUT];
__device__ double g_sum[COUT];
__device__ double g_sumsq[COUT];
__device__ int    g_ticket;          // zero-init at load; k_out resets it

// ---------------------------------------------------------------------------
__device__ __forceinline__ float wsum(float v) {
    #pragma unroll
    for (int d = 16; d; d >>= 1) v += __shfl_xor_sync(0xFFFFFFFFu, v, d);
    return v;
}

// ---------------------------------------------------------------------------
// Kernel 1: warp-per-pillar. Lane p stages point p (coalesced LDG.128) into a
// warp-private smem slab; butterfly-reduces unmasked xyz sums (reference sums
// all 32 points, divides by nv) and masked xyzw sums (for the analytic
// per-channel sum). Then each lane computes channels (lane, lane+32) over the
// nv valid points: dot4 + per-pillar max/min + running sum-of-squares.
// Channel sums are collapsed analytically (no in-loop accumulation).
// ---------------------------------------------------------------------------
__global__ __launch_bounds__(256, 4)
void k_stats(const float4* __restrict__ feats,
             const int*    __restrict__ nvox,
             const int*    __restrict__ coords,
             const float*  __restrict__ W)
{
    __shared__ float4 shp[8][PPTS];          // per-warp slabs
    __shared__ float  rs0[256], rs1[256], rq0[256], rq1[256];

    const int t    = threadIdx.x;
    const int w    = t >> 5;
    const int lane = t & 31;

    // Channel weights: channel A = lane, channel B = lane + 32
    const float* WA = W + lane * 10;
    const float* WB = W + (lane + 32) * 10;
    const float a4 = __ldg(WA+4), a5 = __ldg(WA+5), a6 = __ldg(WA+6);
    const float a7 = __ldg(WA+7), a8 = __ldg(WA+8), a9 = __ldg(WA+9);
    const float ea0 = __ldg(WA+0) + a4 + a7;
    const float ea1 = __ldg(WA+1) + a5 + a8;
    const float ea2 = __ldg(WA+2) + a6 + a9;
    const float ea3 = __ldg(WA+3);
    const float b4 = __ldg(WB+4), b5 = __ldg(WB+5), b6 = __ldg(WB+6);
    const float b7 = __ldg(WB+7), b8 = __ldg(WB+8), b9 = __ldg(WB+9);
    const float eb0 = __ldg(WB+0) + b4 + b7;
    const float eb1 = __ldg(WB+1) + b5 + b8;
    const float eb2 = __ldg(WB+2) + b6 + b9;
    const float eb3 = __ldg(WB+3);

    float sA = 0.0f, sB = 0.0f;      // running channel sums (across pillars)
    float qA = 0.0f, qB = 0.0f;      // running channel sums of squares

    const int gwarp   = blockIdx.x * 8 + w;
    const int nwarps  = STATS_BLOCKS * 8;

    for (int pil = gwarp; pil < NPIL; pil += nwarps) {
        const float4 pt = feats[pil * PPTS + lane];   // coalesced 512B/pillar
        __syncwarp();                 // prior iteration's readers done
        shp[w][lane] = pt;

        const int   nv  = __ldg(&nvox[pil]);          // same-addr broadcast
        const float nvf = (float)nv;
        const float rnv = 1.0f / nvf;
        const int   c1  = __ldg(&coords[pil * 4 + 1]);
        const int   c2  = __ldg(&coords[pil * 4 + 2]);
        const int   c3  = __ldg(&coords[pil * 4 + 3]);
        const float cz  = (float)c1 * 4.0f - 1.0f;
        const float cy  = (float)c2 * 0.2f - 39.9f;
        const float cx  = (float)c3 * 0.2f + 0.1f;

        // Reductions: unmasked xyz (for mean), masked xyzw (for analytic sum)
        const bool valid = lane < nv;
        const float mmx = wsum(pt.x) * rnv;           // mean x (unmasked sum!)
        const float mmy = wsum(pt.y) * rnv;
        const float mmz = wsum(pt.z) * rnv;
        const float Sxm = wsum(valid ? pt.x : 0.0f);
        const float Sym = wsum(valid ? pt.y : 0.0f);
        const float Szm = wsum(valid ? pt.z : 0.0f);
        const float Swm = wsum(valid ? pt.w : 0.0f);
        __syncwarp();                 // slab visible to all lanes

        // const_n[c] = -mean.W[4:7] - center.W[7:10]
        const float cstA = -fmaf(mmx, a4, fmaf(mmy, a5, fmaf(mmz, a6,
                            fmaf(cx, a7, fmaf(cy, a8, cz * a9)))));
        const float cstB = -fmaf(mmx, b4, fmaf(mmy, b5, fmaf(mmz, b6,
                            fmaf(cx, b7, fmaf(cy, b8, cz * b9)))));

        // Analytic per-channel sums over valid points
        sA += fmaf(ea0, Sxm, fmaf(ea1, Sym, fmaf(ea2, Szm,
              fmaf(ea3, Swm, nvf * cstA))));
        sB += fmaf(eb0, Sxm, fmaf(eb1, Sym, fmaf(eb2, Szm,
              fmaf(eb3, Swm, nvf * cstB))));

        float mxA = -FLT_MAX, mnA = FLT_MAX;
        float mxB = -FLT_MAX, mnB = FLT_MAX;
        #pragma unroll 2
        for (int p = 0; p < nv; p++) {
            const float4 q = shp[w][p];               // same-addr LDS.128
            const float vA = fmaf(ea0, q.x, fmaf(ea1, q.y,
                             fmaf(ea2, q.z, fmaf(ea3, q.w, cstA))));
            const float vB = fmaf(eb0, q.x, fmaf(eb1, q.y,
                             fmaf(eb2, q.z, fmaf(eb3, q.w, cstB))));
            mxA = fmaxf(mxA, vA);  mnA = fminf(mnA, vA);
            mxB = fmaxf(mxB, vB);  mnB = fminf(mnB, vB);
            qA  = fmaf(vA, vA, qA);
            qB  = fmaf(vB, vB, qB);
        }
        if (nv < PPTS) {              // masked points are exact zeros
            mxA = fmaxf(mxA, 0.0f);  mnA = fminf(mnA, 0.0f);
            mxB = fmaxf(mxB, 0.0f);  mnB = fminf(mnB, 0.0f);
        }
        g_pmax[pil * COUT + lane]      = mxA;
        g_pmax[pil * COUT + lane + 32] = mxB;
        g_pmin[pil * COUT + lane]      = mnA;
        g_pmin[pil * COUT + lane + 32] = mnB;
    }

    // ---- block reduction: lane l of every warp holds channels l, l+32 ----
    rs0[t] = sA;  rs1[t] = sB;  rq0[t] = qA;  rq1[t] = qB;
    __syncthreads();
    if (t < COUT) {
        double s = 0.0, q = 0.0;
        if (t < 32) {
            #pragma unroll
            for (int ww = 0; ww < 8; ww++) { s += (double)rs0[t + 32*ww]; q += (double)rq0[t + 32*ww]; }
        } else {
            #pragma unroll
            for (int ww = 0; ww < 8; ww++) { s += (double)rs1[(t-32) + 32*ww]; q += (double)rq1[(t-32) + 32*ww]; }
        }
        atomicAdd(&g_sum[t],   s);
        atomicAdd(&g_sumsq[t], q);
    }
}

// ---------------------------------------------------------------------------
// Kernel 2: finalize BN per block, stream scratch -> affine -> relu -> out.
// Ticket-zeroing: the last block to have READ the accumulators zeroes them
// for the next graph replay (every block increments only after its reads).
// ---------------------------------------------------------------------------
__global__ __launch_bounds__(256)
void k_out(const float* __restrict__ gamma,
           const float* __restrict__ beta,
           float4* __restrict__ out)
{
    __shared__ float4 sc4[16];
    __shared__ float4 sb4[16];
    const int t = threadIdx.x;
    if (t < COUT) {
        const double m   = g_sum[t]   / NTOT;
        const double var = g_sumsq[t] / NTOT - m * m;
        const float  s   = gamma[t] / (float)sqrt(var + 1e-3);
        ((float*)sc4)[t] = s;
        ((float*)sb4)[t] = beta[t] - (float)m * s;
    }
    __syncthreads();
    if (t == 0) {                          // reads done; safe to ticket
        const int r = atomicAdd(&g_ticket, 1);
        if (r == (int)gridDim.x - 1) {
            #pragma unroll
            for (int i = 0; i < COUT; i++) { g_sum[i] = 0.0; g_sumsq[i] = 0.0; }
            g_ticket = 0;
        }
    }

    const float4* __restrict__ pmx = (const float4*)g_pmax;
    const float4* __restrict__ pmn = (const float4*)g_pmin;
    const int total  = NPIL * COUT / 4;
    const int stride = gridDim.x * blockDim.x;
    for (int idx = blockIdx.x * blockDim.x + t; idx < total; idx += stride) {
        const int grp = idx & 15;
        const float4 s4 = sc4[grp];
        const float4 b4 = sb4[grp];
        const bool pos = (s4.x >= 0.f) & (s4.y >= 0.f) & (s4.z >= 0.f) & (s4.w >= 0.f);
        const bool neg = (s4.x <  0.f) & (s4.y <  0.f) & (s4.z <  0.f) & (s4.w <  0.f);
        float4 e;
        if (pos)       e = pmx[idx];
        else if (neg)  e = pmn[idx];
        else {
            const float4 a = pmx[idx], c = pmn[idx];
            e.x = (s4.x >= 0.f) ? a.x : c.x;
            e.y = (s4.y >= 0.f) ? a.y : c.y;
            e.z = (s4.z >= 0.f) ? a.z : c.z;
            e.w = (s4.w >= 0.f) ? a.w : c.w;
        }
        float4 o;
        o.x = fmaxf(0.0f, fmaf(s4.x, e.x, b4.x));
        o.y = fmaxf(0.0f, fmaf(s4.y, e.y, b4.y));
        o.z = fmaxf(0.0f, fmaf(s4.z, e.z, b4.z));
        o.w = fmaxf(0.0f, fmaf(s4.w, e.w, b4.w));
        out[idx] = o;
    }
}

// ---------------------------------------------------------------------------
extern "C" void kernel_launch(void* const* d_in, const int* in_sizes, int n_in,
                              void* d_out, int out_size)
{
    const float4* feats  = (const float4*)d_in[0];
    const int*    nvox   = (const int*)   d_in[1];
    const int*    coords = (const int*)   d_in[2];
    const float*  W      = (const float*) d_in[3];
    const float*  gamma  = (const float*) d_in[4];
    const float*  beta   = (const float*) d_in[5];
    float4*       out    = (float4*)      d_out;

    k_stats<<<STATS_BLOCKS, 256>>>(feats, nvox, coords, W);
    k_out<<<OUT_BLOCKS, 256>>>(gamma, beta, out);
}